// round 9
// baseline (speedup 1.0000x reference)
#include <cuda_runtime.h>
#include <cuda_bf16.h>
#include <cstdint>

#define VQ   50257
#define EMBQ 512
typedef unsigned long long ull;

// ------------------------------ scratch -------------------------------------
__device__ float2 g_cs[256 * 64];   // per (b,w) gate (cos(th/2), sin(th/2))
__device__ float2 g_qcs[32];        // qff gate table
__device__ float2 g_coeffs[16];     // normalized mix coefficients
__device__ float2 g_st[256 * 256];  // per-(b,w) states (slot = r*32+lane)
__device__ float2 g_work[16 * 256]; // reduced work state per batch
__device__ float2 g_acc[16 * 256];  // polynomial accumulator
__device__ float  g_fp[16];         // final_probs
__device__ ull    g_hp[512 * 8];    // h packed: [k*8+bp] = f32x2(h[2bp][k], h[2bp+1][k])

// ------------------------------ f32x2 helpers --------------------------------
__device__ __forceinline__ ull dup2(float a) {
    ull r; asm("mov.b64 %0, {%1, %1};" : "=l"(r) : "f"(a)); return r;
}
__device__ __forceinline__ void ffma2(ull& d, ull a, ull b) {
    asm("fma.rn.f32x2 %0, %1, %2, %0;" : "+l"(d) : "l"(a), "l"(b));
}
__device__ __forceinline__ void unpack2(ull v, float& lo, float& hi) {
    asm("mov.b64 {%0, %1}, %2;" : "=f"(lo), "=f"(hi) : "l"(v));
}
__device__ __forceinline__ void cp16(uint32_t dst, const void* src) {
    asm volatile("cp.async.cg.shared.global [%0], [%1], 16;" :: "r"(dst), "l"(src));
}

// =============================================================================
// Warp-resident 8-qubit sim. Amp index i: lane = i>>3 (bits 7..3), r = i&7.
// Qubit w <-> bit (7-w): w<=4 -> lane bit (1<<(4-w)); w>=5 -> reg bit (1<<(7-w)).
// =============================================================================
template <int W>
__device__ __forceinline__ void ry_t(float2 st[8], float2 g, int lane) {
    const float c = g.x, s = g.y;
    if constexpr (W >= 5) {
        constexpr int m = 1 << (7 - W);
#pragma unroll
        for (int r = 0; r < 8; r++) if (!(r & m)) {
            float2 a0 = st[r], a1 = st[r | m];
            st[r]     = make_float2(c * a0.x - s * a1.x, c * a0.y - s * a1.y);
            st[r | m] = make_float2(s * a0.x + c * a1.x, s * a0.y + c * a1.y);
        }
    } else {
        constexpr int lm = 1 << (4 - W);
        const float sg = (lane & lm) ? s : -s;
#pragma unroll
        for (int r = 0; r < 8; r++) {
            float px = __shfl_xor_sync(0xffffffffu, st[r].x, lm);
            float py = __shfl_xor_sync(0xffffffffu, st[r].y, lm);
            st[r].x = fmaf(sg, px, c * st[r].x);
            st[r].y = fmaf(sg, py, c * st[r].y);
        }
    }
}

// CRX (control bit==1): new = c*mine + s*(partner.y, -partner.x)  (symmetric)
template <int C, int T>
__device__ __forceinline__ void crx_t(float2 st[8], float2 g, int lane) {
    const float c = g.x, s = g.y;
    if constexpr (C >= 5) {
        constexpr int cm = 1 << (7 - C);
        if constexpr (T >= 5) {
            constexpr int tm = 1 << (7 - T);
#pragma unroll
            for (int r = 0; r < 8; r++) if ((r & cm) && !(r & tm)) {
                float2 a0 = st[r], a1 = st[r | tm];
                st[r]      = make_float2(c * a0.x + s * a1.y, c * a0.y - s * a1.x);
                st[r | tm] = make_float2(c * a1.x + s * a0.y, c * a1.y - s * a0.x);
            }
        } else {
            constexpr int tlm = 1 << (4 - T);
#pragma unroll
            for (int r = 0; r < 8; r++) {
                float px = __shfl_xor_sync(0xffffffffu, st[r].x, tlm);
                float py = __shfl_xor_sync(0xffffffffu, st[r].y, tlm);
                if (r & cm) {
                    st[r].x = fmaf(s, py, c * st[r].x);
                    st[r].y = fmaf(-s, px, c * st[r].y);
                }
            }
        }
    } else {
        constexpr int clm = 1 << (4 - C);
        const bool act = (lane & clm) != 0;
        if constexpr (T >= 5) {
            constexpr int tm = 1 << (7 - T);
#pragma unroll
            for (int r = 0; r < 8; r++) if (!(r & tm)) {
                float2 a0 = st[r], a1 = st[r | tm];
                if (act) {
                    st[r]      = make_float2(c * a0.x + s * a1.y, c * a0.y - s * a1.x);
                    st[r | tm] = make_float2(c * a1.x + s * a0.y, c * a1.y - s * a0.x);
                }
            }
        } else {
            constexpr int tlm = 1 << (4 - T);
#pragma unroll
            for (int r = 0; r < 8; r++) {
                float px = __shfl_xor_sync(0xffffffffu, st[r].x, tlm);
                float py = __shfl_xor_sync(0xffffffffu, st[r].y, tlm);
                if (act) {
                    st[r].x = fmaf(s, py, c * st[r].x);
                    st[r].y = fmaf(-s, px, c * st[r].y);
                }
            }
        }
    }
}

// one sim14 layer = 32 gates
__device__ __forceinline__ void sim_layer(float2 st[8], const float2* cs, int lane) {
    int k = 0;
    ry_t<0>(st, cs[k++], lane); ry_t<1>(st, cs[k++], lane); ry_t<2>(st, cs[k++], lane);
    ry_t<3>(st, cs[k++], lane); ry_t<4>(st, cs[k++], lane); ry_t<5>(st, cs[k++], lane);
    ry_t<6>(st, cs[k++], lane); ry_t<7>(st, cs[k++], lane);
    crx_t<7,0>(st, cs[k++], lane); crx_t<6,7>(st, cs[k++], lane); crx_t<5,6>(st, cs[k++], lane);
    crx_t<4,5>(st, cs[k++], lane); crx_t<3,4>(st, cs[k++], lane); crx_t<2,3>(st, cs[k++], lane);
    crx_t<1,2>(st, cs[k++], lane); crx_t<0,1>(st, cs[k++], lane);
    ry_t<0>(st, cs[k++], lane); ry_t<1>(st, cs[k++], lane); ry_t<2>(st, cs[k++], lane);
    ry_t<3>(st, cs[k++], lane); ry_t<4>(st, cs[k++], lane); ry_t<5>(st, cs[k++], lane);
    ry_t<6>(st, cs[k++], lane); ry_t<7>(st, cs[k++], lane);
    crx_t<7,6>(st, cs[k++], lane); crx_t<0,7>(st, cs[k++], lane); crx_t<1,0>(st, cs[k++], lane);
    crx_t<2,1>(st, cs[k++], lane); crx_t<3,2>(st, cs[k++], lane); crx_t<4,3>(st, cs[k++], lane);
    crx_t<5,4>(st, cs[k++], lane); crx_t<6,5>(st, cs[k++], lane);
}

// =============================================================================
// k_emb: grid 64, 256 thr; 4 states/block.  wparams -> (cos,sin) tables.
// =============================================================================
__global__ void __launch_bounds__(256) k_emb(
    const int* __restrict__ x, const float* __restrict__ embW,
    const float* __restrict__ e2rW, const float* __restrict__ e2rb,
    const float* __restrict__ mix, const float* __restrict__ qff) {
    __shared__ float emb[4][EMBQ];
    __shared__ int sx[4];
    int tid = threadIdx.x, s0 = blockIdx.x * 4;
    if (tid < 4) sx[tid] = x[s0 + tid];
    __syncthreads();
    for (int u = tid; u < 4 * EMBQ; u += 256)
        emb[u >> 9][u & 511] = embW[(size_t)sx[u >> 9] * EMBQ + (u & 511)];
    __syncthreads();
    int wid = tid >> 5, lane = tid & 31;
#pragma unroll 1
    for (int jj = 0; jj < 8; jj++) {
        int j = jj * 8 + wid;
        float p0 = 0.f, p1 = 0.f, p2 = 0.f, p3 = 0.f;
        const float* wr = e2rW + (size_t)j * EMBQ;
        for (int k = lane; k < EMBQ; k += 32) {
            float wv = wr[k];
            p0 = fmaf(emb[0][k], wv, p0); p1 = fmaf(emb[1][k], wv, p1);
            p2 = fmaf(emb[2][k], wv, p2); p3 = fmaf(emb[3][k], wv, p3);
        }
#pragma unroll
        for (int o = 16; o; o >>= 1) {
            p0 += __shfl_xor_sync(0xffffffffu, p0, o);
            p1 += __shfl_xor_sync(0xffffffffu, p1, o);
            p2 += __shfl_xor_sync(0xffffffffu, p2, o);
            p3 += __shfl_xor_sync(0xffffffffu, p3, o);
        }
        if (lane == 0) {
            float bj = e2rb[j];
            float ps[4] = {p0, p1, p2, p3};
#pragma unroll
            for (int st = 0; st < 4; st++) {
                float sn, cn; sincosf(0.5f * (ps[st] + bj), &sn, &cn);
                g_cs[(s0 + st) * 64 + j] = make_float2(cn, sn);
            }
        }
    }
    if (blockIdx.x == 0 && wid == 0) {
        float re = 0.f, im = 0.f, a = 0.f;
        if (lane < 16) { re = mix[2 * lane]; im = mix[2 * lane + 1]; a = sqrtf(re * re + im * im); }
        float s = a;
#pragma unroll
        for (int o = 16; o; o >>= 1) s += __shfl_xor_sync(0xffffffffu, s, o);
        s = fmaxf(s, 1e-12f);
        if (lane < 16) g_coeffs[lane] = make_float2(re / s, im / s);
    }
    if (blockIdx.x == 0 && wid == 1) {
        float sn, cn; sincosf(0.5f * qff[lane], &sn, &cn);
        g_qcs[lane] = make_float2(cn, sn);
    }
}

// =============================================================================
// k_deg: grid 256 (b*16+w), 32 threads: warp-resident 2-layer sim14.
// =============================================================================
template <bool FIRST>
__global__ void __launch_bounds__(32) k_deg() {
    __shared__ float2 cs[64];
    int lane = threadIdx.x, blk = blockIdx.x, b = blk >> 4;
    cs[lane]      = g_cs[blk * 64 + lane];
    cs[lane + 32] = g_cs[blk * 64 + 32 + lane];
    float2 st[8];
#pragma unroll
    for (int r = 0; r < 8; r++) {
        if (FIRST) st[r] = make_float2((lane == 0 && r == 0) ? 1.f : 0.f, 0.f);
        else       st[r] = g_work[b * 256 + r * 32 + lane];
    }
    __syncwarp();
#pragma unroll 1
    for (int l = 0; l < 2; l++) sim_layer(st, cs + l * 32, lane);
#pragma unroll
    for (int r = 0; r < 8; r++) g_st[blk * 256 + r * 32 + lane] = st[r];
}

// =============================================================================
// k_red: grid 16 (batch), 256 threads: word reduction + poly accumulate.
// =============================================================================
template <int D>
__global__ void __launch_bounds__(256) k_red(const float* __restrict__ poly) {
    int i = threadIdx.x, b = blockIdx.x;
    float2 red = make_float2(0.f, 0.f);
#pragma unroll
    for (int w = 0; w < 16; w++) {
        float2 c = g_coeffs[w];
        float2 s = g_st[(b * 16 + w) * 256 + i];
        red.x = fmaf(s.x, c.x, fmaf(-s.y, c.y, red.x));
        red.y = fmaf(s.x, c.y, fmaf(s.y, c.x, red.y));
    }
    g_work[b * 256 + i] = red;
    float pd = poly[D];
    float2 a;
    if (D == 1) a = make_float2(pd * red.x + (i == 0 ? poly[0] : 0.f), pd * red.y);
    else { a = g_acc[b * 256 + i]; a.x = fmaf(pd, red.x, a.x); a.y = fmaf(pd, red.y, a.y); }
    g_acc[b * 256 + i] = a;
}

// =============================================================================
// k_post: grid 16, 32 threads: normalize, qff sim, measure, ff1.
// =============================================================================
__global__ void __launch_bounds__(32) k_post(const float* __restrict__ poly,
                                             const float* __restrict__ ff1W,
                                             const float* __restrict__ ff1b) {
    __shared__ float2 qcs[32];
    int lane = threadIdx.x, b = blockIdx.x;
    qcs[lane] = g_qcs[lane];
    float invp = 1.f / (fabsf(poly[0]) + fabsf(poly[1]) + fabsf(poly[2]) + fabsf(poly[3]));
    float2 st[8];
    float pn = 0.f;
#pragma unroll
    for (int r = 0; r < 8; r++) {
        float2 a = g_acc[b * 256 + r * 32 + lane];
        st[r] = make_float2(a.x * invp, a.y * invp);
        pn += st[r].x * st[r].x + st[r].y * st[r].y;
    }
#pragma unroll
    for (int o = 16; o; o >>= 1) pn += __shfl_xor_sync(0xffffffffu, pn, o);
    float fp = sqrtf(pn);
    if (lane == 0) g_fp[b] = fp;
    float inv = 1.f / fmaxf(fp, 1e-12f);
#pragma unroll
    for (int r = 0; r < 8; r++) { st[r].x *= inv; st[r].y *= inv; }
    __syncwarp();
    sim_layer(st, qcs, lane);

    float exr[24];
#define MEAS_REG(W_) { constexpr int m = 1 << (7 - (W_)); \
    float cr = 0.f, ci = 0.f, zz = 0.f; \
    _Pragma("unroll") \
    for (int r = 0; r < 8; r++) if (!(r & m)) { \
        float2 a0 = st[r], a1 = st[r | m]; \
        cr += a0.x * a1.x + a0.y * a1.y; \
        ci += a0.x * a1.y - a0.y * a1.x; \
        zz += a0.x * a0.x + a0.y * a0.y - a1.x * a1.x - a1.y * a1.y; } \
    _Pragma("unroll") \
    for (int o = 16; o; o >>= 1) { \
        cr += __shfl_xor_sync(0xffffffffu, cr, o); \
        ci += __shfl_xor_sync(0xffffffffu, ci, o); \
        zz += __shfl_xor_sync(0xffffffffu, zz, o); } \
    exr[(W_)] = 2.f * cr; exr[8 + (W_)] = 2.f * ci; exr[16 + (W_)] = zz; }

#define MEAS_LANE(W_) { constexpr int lm = 1 << (4 - (W_)); \
    bool hi = (lane & lm) != 0; \
    float cr = 0.f, ci = 0.f, zz = 0.f; \
    _Pragma("unroll") \
    for (int r = 0; r < 8; r++) { \
        float px = __shfl_xor_sync(0xffffffffu, st[r].x, lm); \
        float py = __shfl_xor_sync(0xffffffffu, st[r].y, lm); \
        float n2 = st[r].x * st[r].x + st[r].y * st[r].y; \
        if (!hi) { cr += st[r].x * px + st[r].y * py; \
                   ci += st[r].x * py - st[r].y * px; zz += n2; } \
        else zz -= n2; } \
    _Pragma("unroll") \
    for (int o = 16; o; o >>= 1) { \
        cr += __shfl_xor_sync(0xffffffffu, cr, o); \
        ci += __shfl_xor_sync(0xffffffffu, ci, o); \
        zz += __shfl_xor_sync(0xffffffffu, zz, o); } \
    exr[(W_)] = 2.f * cr; exr[8 + (W_)] = 2.f * ci; exr[16 + (W_)] = zz; }

    MEAS_LANE(0); MEAS_LANE(1); MEAS_LANE(2); MEAS_LANE(3); MEAS_LANE(4);
    MEAS_REG(5);  MEAS_REG(6);  MEAS_REG(7);

    // ff1 (all lanes have full exr)
#pragma unroll 1
    for (int j = lane; j < EMBQ; j += 32) {
        float h = ff1b[j];
        const float* wr = ff1W + j * 24;
#pragma unroll
        for (int m = 0; m < 24; m++) h = fmaf(exr[m], wr[m], h);
        h = fmaxf(h, 0.f);
        ((float*)&g_hp[j * 8 + (b >> 1)])[b & 1] = h;
    }
}

// =============================================================================
// k_ff2: 148 blocks x 256 thr, 340 rows/block, cp.async double-buffered.
// =============================================================================
#define FF2_ROWS   340
#define FF2_STRIDE 36
#define FF2_BUF    (FF2_ROWS * FF2_STRIDE)          // floats per buffer
#define FF2_SMEM   (32768 + 2 * FF2_BUF * 4)

__device__ __forceinline__ void ff2_stage(float* buf, const float* __restrict__ W2,
                                          int base, int k0, int tid) {
    uint32_t sb = (uint32_t)__cvta_generic_to_shared(buf);
#pragma unroll 1
    for (int u = tid; u < FF2_ROWS * 8; u += 256) {
        int rr = u >> 3, q = u & 7;
        int v = base + rr; if (v >= VQ) v = VQ - 1;
        cp16(sb + (uint32_t)(rr * FF2_STRIDE + q * 4) * 4,
             W2 + (size_t)v * EMBQ + k0 + q * 4);
    }
}

__global__ void __launch_bounds__(256) k_ff2(const float* __restrict__ W2,
                                             const float* __restrict__ b2,
                                             float* __restrict__ out, int out_size) {
    extern __shared__ char dsm[];
    ull*   hsh = (ull*)dsm;                          // 32 KB
    float* sW0 = (float*)(dsm + 32768);
    float* sW1 = sW0 + FF2_BUF;
    const ulonglong2* hsh2 = (const ulonglong2*)hsh;

    int t = threadIdx.x;
    int base = blockIdx.x * FF2_ROWS;
    bool has2 = (256 + t) < FF2_ROWS;                // t < 84

    for (int i = t; i < 4096; i += 256) hsh[i] = g_hp[i];

    ff2_stage(sW0, W2, base, 0, t);
    asm volatile("cp.async.commit_group;");

    ull acc0[8], acc1[8];
#pragma unroll
    for (int bp = 0; bp < 8; bp++) { acc0[bp] = 0ull; acc1[bp] = 0ull; }

#pragma unroll 1
    for (int c = 0; c < 16; c++) {
        if (c < 15) {
            ff2_stage((c & 1) ? sW0 : sW1, W2, base, (c + 1) * 32, t);
            asm volatile("cp.async.commit_group;");
            asm volatile("cp.async.wait_group 1;");
        } else {
            asm volatile("cp.async.wait_group 0;");
        }
        __syncthreads();
        const float4* b4 = (const float4*)((c & 1) ? sW1 : sW0);
        int k0 = c * 32;
#pragma unroll
        for (int q = 0; q < 8; q++) {
            float4 wA = b4[t * 9 + q];
            float4 wB = make_float4(0.f, 0.f, 0.f, 0.f);
            if (has2) wB = b4[(256 + t) * 9 + q];
            float wa[4] = {wA.x, wA.y, wA.z, wA.w};
            float wb[4] = {wB.x, wB.y, wB.z, wB.w};
            const ulonglong2* hp = hsh2 + (size_t)(k0 + q * 4) * 4;
#pragma unroll
            for (int j = 0; j < 4; j++) {
                ulonglong2 h01 = hp[j * 4 + 0], h23 = hp[j * 4 + 1];
                ulonglong2 h45 = hp[j * 4 + 2], h67 = hp[j * 4 + 3];
                ull WA = dup2(wa[j]);
                ffma2(acc0[0], h01.x, WA); ffma2(acc0[1], h01.y, WA);
                ffma2(acc0[2], h23.x, WA); ffma2(acc0[3], h23.y, WA);
                ffma2(acc0[4], h45.x, WA); ffma2(acc0[5], h45.y, WA);
                ffma2(acc0[6], h67.x, WA); ffma2(acc0[7], h67.y, WA);
                if (has2) {
                    ull WB = dup2(wb[j]);
                    ffma2(acc1[0], h01.x, WB); ffma2(acc1[1], h01.y, WB);
                    ffma2(acc1[2], h23.x, WB); ffma2(acc1[3], h23.y, WB);
                    ffma2(acc1[4], h45.x, WB); ffma2(acc1[5], h45.y, WB);
                    ffma2(acc1[6], h67.x, WB); ffma2(acc1[7], h67.y, WB);
                }
            }
        }
        __syncthreads();
    }

    int r0 = base + t;
    if (r0 < VQ) {
        float bias = b2[r0];
#pragma unroll
        for (int bp = 0; bp < 8; bp++) {
            float lo, hi; unpack2(acc0[bp], lo, hi);
            out[(size_t)(2 * bp) * VQ + r0]     = lo + bias;
            out[(size_t)(2 * bp + 1) * VQ + r0] = hi + bias;
        }
    }
    int r1 = base + 256 + t;
    if (has2 && r1 < VQ) {
        float bias = b2[r1];
#pragma unroll
        for (int bp = 0; bp < 8; bp++) {
            float lo, hi; unpack2(acc1[bp], lo, hi);
            out[(size_t)(2 * bp) * VQ + r1]     = lo + bias;
            out[(size_t)(2 * bp + 1) * VQ + r1] = hi + bias;
        }
    }
    if (blockIdx.x == 0 && t == 0 && out_size > 16 * VQ) {
        float s = 0.f;
        for (int b = 0; b < 16; b++) s += g_fp[b];
        out[16 * VQ] = s * (1.f / 16.f);
    }
}

// ------------------------------ launch ---------------------------------------
extern "C" void kernel_launch(void* const* d_in, const int* in_sizes, int n_in,
                              void* d_out, int out_size) {
    const int*   x    = (const int*)  d_in[0];
    const float* embW = (const float*)d_in[1];
    const float* e2rW = (const float*)d_in[2];
    const float* e2rb = (const float*)d_in[3];
    const float* poly = (const float*)d_in[4];
    const float* mix  = (const float*)d_in[5];
    const float* qff  = (const float*)d_in[6];
    const float* ff1W = (const float*)d_in[7];
    const float* ff1b = (const float*)d_in[8];
    const float* W2   = (const float*)d_in[9];
    const float* b2   = (const float*)d_in[10];
    float* out = (float*)d_out;

    cudaFuncSetAttribute(k_ff2, cudaFuncAttributeMaxDynamicSharedMemorySize, FF2_SMEM);

    k_emb<<<64, 256>>>(x, embW, e2rW, e2rb, mix, qff);
    k_deg<true><<<256, 32>>>();
    k_red<1><<<16, 256>>>(poly);
    k_deg<false><<<256, 32>>>();
    k_red<2><<<16, 256>>>(poly);
    k_deg<false><<<256, 32>>>();
    k_red<3><<<16, 256>>>(poly);
    k_post<<<16, 32>>>(poly, ff1W, ff1b);
    k_ff2<<<148, 256, FF2_SMEM>>>(W2, b2, out, out_size);
}

// round 10
// speedup vs baseline: 1.4507x; 1.4507x over previous
#include <cuda_runtime.h>
#include <cuda_bf16.h>
#include <cstdint>

#define VQ   50257
#define EMBQ 512
typedef unsigned long long ull;

// ------------------------------ scratch -------------------------------------
__device__ float2 g_cs[256 * 64];   // per (b,w) gate (cos(th/2), sin(th/2))
__device__ float2 g_qcs[32];        // qff gate table
__device__ float2 g_coeffs[16];     // normalized mix coefficients
__device__ float  g_fp[16];         // final_probs
__device__ ull    g_hp[512 * 8];    // h packed: [k*8+bp] = f32x2(h[2bp][k], h[2bp+1][k])

// ------------------------------ f32x2 helpers --------------------------------
__device__ __forceinline__ ull dup2(float a) {
    ull r; asm("mov.b64 %0, {%1, %1};" : "=l"(r) : "f"(a)); return r;
}
__device__ __forceinline__ void ffma2(ull& d, ull a, ull b) {
    asm("fma.rn.f32x2 %0, %1, %2, %0;" : "+l"(d) : "l"(a), "l"(b));
}
__device__ __forceinline__ void unpack2(ull v, float& lo, float& hi) {
    asm("mov.b64 {%0, %1}, %2;" : "=f"(lo), "=f"(hi) : "l"(v));
}
__device__ __forceinline__ void cp16(uint32_t dst, const void* src) {
    asm volatile("cp.async.cg.shared.global [%0], [%1], 16;" :: "r"(dst), "l"(src));
}

// =============================================================================
// Warp-resident 8-qubit sim. Amp index i: lane = i>>3 (bits 7..3), r = i&7.
// Qubit w <-> bit (7-w): w<=4 -> lane bit (1<<(4-w)); w>=5 -> reg bit (1<<(7-w)).
// =============================================================================
template <int W>
__device__ __forceinline__ void ry_t(float2 st[8], float2 g, int lane) {
    const float c = g.x, s = g.y;
    if constexpr (W >= 5) {
        constexpr int m = 1 << (7 - W);
#pragma unroll
        for (int r = 0; r < 8; r++) if (!(r & m)) {
            float2 a0 = st[r], a1 = st[r | m];
            st[r]     = make_float2(c * a0.x - s * a1.x, c * a0.y - s * a1.y);
            st[r | m] = make_float2(s * a0.x + c * a1.x, s * a0.y + c * a1.y);
        }
    } else {
        constexpr int lm = 1 << (4 - W);
        const float sg = (lane & lm) ? s : -s;
#pragma unroll
        for (int r = 0; r < 8; r++) {
            float px = __shfl_xor_sync(0xffffffffu, st[r].x, lm);
            float py = __shfl_xor_sync(0xffffffffu, st[r].y, lm);
            st[r].x = fmaf(sg, px, c * st[r].x);
            st[r].y = fmaf(sg, py, c * st[r].y);
        }
    }
}

// CRX (control bit==1): new = c*mine + s*(partner.y, -partner.x)
template <int C, int T>
__device__ __forceinline__ void crx_t(float2 st[8], float2 g, int lane) {
    const float c = g.x, s = g.y;
    if constexpr (C >= 5) {
        constexpr int cm = 1 << (7 - C);
        if constexpr (T >= 5) {
            constexpr int tm = 1 << (7 - T);
#pragma unroll
            for (int r = 0; r < 8; r++) if ((r & cm) && !(r & tm)) {
                float2 a0 = st[r], a1 = st[r | tm];
                st[r]      = make_float2(c * a0.x + s * a1.y, c * a0.y - s * a1.x);
                st[r | tm] = make_float2(c * a1.x + s * a0.y, c * a1.y - s * a0.x);
            }
        } else {
            constexpr int tlm = 1 << (4 - T);
#pragma unroll
            for (int r = 0; r < 8; r++) {
                float px = __shfl_xor_sync(0xffffffffu, st[r].x, tlm);
                float py = __shfl_xor_sync(0xffffffffu, st[r].y, tlm);
                if (r & cm) {
                    st[r].x = fmaf(s, py, c * st[r].x);
                    st[r].y = fmaf(-s, px, c * st[r].y);
                }
            }
        }
    } else {
        constexpr int clm = 1 << (4 - C);
        const bool act = (lane & clm) != 0;
        if constexpr (T >= 5) {
            constexpr int tm = 1 << (7 - T);
#pragma unroll
            for (int r = 0; r < 8; r++) if (!(r & tm)) {
                float2 a0 = st[r], a1 = st[r | tm];
                if (act) {
                    st[r]      = make_float2(c * a0.x + s * a1.y, c * a0.y - s * a1.x);
                    st[r | tm] = make_float2(c * a1.x + s * a0.y, c * a1.y - s * a0.x);
                }
            }
        } else {
            constexpr int tlm = 1 << (4 - T);
#pragma unroll
            for (int r = 0; r < 8; r++) {
                float px = __shfl_xor_sync(0xffffffffu, st[r].x, tlm);
                float py = __shfl_xor_sync(0xffffffffu, st[r].y, tlm);
                if (act) {
                    st[r].x = fmaf(s, py, c * st[r].x);
                    st[r].y = fmaf(-s, px, c * st[r].y);
                }
            }
        }
    }
}

__device__ __forceinline__ void sim_layer(float2 st[8], const float2* cs, int lane) {
    int k = 0;
    ry_t<0>(st, cs[k++], lane); ry_t<1>(st, cs[k++], lane); ry_t<2>(st, cs[k++], lane);
    ry_t<3>(st, cs[k++], lane); ry_t<4>(st, cs[k++], lane); ry_t<5>(st, cs[k++], lane);
    ry_t<6>(st, cs[k++], lane); ry_t<7>(st, cs[k++], lane);
    crx_t<7,0>(st, cs[k++], lane); crx_t<6,7>(st, cs[k++], lane); crx_t<5,6>(st, cs[k++], lane);
    crx_t<4,5>(st, cs[k++], lane); crx_t<3,4>(st, cs[k++], lane); crx_t<2,3>(st, cs[k++], lane);
    crx_t<1,2>(st, cs[k++], lane); crx_t<0,1>(st, cs[k++], lane);
    ry_t<0>(st, cs[k++], lane); ry_t<1>(st, cs[k++], lane); ry_t<2>(st, cs[k++], lane);
    ry_t<3>(st, cs[k++], lane); ry_t<4>(st, cs[k++], lane); ry_t<5>(st, cs[k++], lane);
    ry_t<6>(st, cs[k++], lane); ry_t<7>(st, cs[k++], lane);
    crx_t<7,6>(st, cs[k++], lane); crx_t<0,7>(st, cs[k++], lane); crx_t<1,0>(st, cs[k++], lane);
    crx_t<2,1>(st, cs[k++], lane); crx_t<3,2>(st, cs[k++], lane); crx_t<4,3>(st, cs[k++], lane);
    crx_t<5,4>(st, cs[k++], lane); crx_t<6,5>(st, cs[k++], lane);
}

// =============================================================================
// k_emb: grid 64, 256 thr; 4 states/block.  wparams -> (cos,sin) tables.
// =============================================================================
__global__ void __launch_bounds__(256) k_emb(
    const int* __restrict__ x, const float* __restrict__ embW,
    const float* __restrict__ e2rW, const float* __restrict__ e2rb,
    const float* __restrict__ mix, const float* __restrict__ qff) {
    __shared__ float emb[4][EMBQ];
    __shared__ int sx[4];
    int tid = threadIdx.x, s0 = blockIdx.x * 4;
    if (tid < 4) sx[tid] = x[s0 + tid];
    __syncthreads();
    for (int u = tid; u < 4 * EMBQ; u += 256)
        emb[u >> 9][u & 511] = embW[(size_t)sx[u >> 9] * EMBQ + (u & 511)];
    __syncthreads();
    int wid = tid >> 5, lane = tid & 31;
#pragma unroll 1
    for (int jj = 0; jj < 8; jj++) {
        int j = jj * 8 + wid;
        float p0 = 0.f, p1 = 0.f, p2 = 0.f, p3 = 0.f;
        const float* wr = e2rW + (size_t)j * EMBQ;
        for (int k = lane; k < EMBQ; k += 32) {
            float wv = wr[k];
            p0 = fmaf(emb[0][k], wv, p0); p1 = fmaf(emb[1][k], wv, p1);
            p2 = fmaf(emb[2][k], wv, p2); p3 = fmaf(emb[3][k], wv, p3);
        }
#pragma unroll
        for (int o = 16; o; o >>= 1) {
            p0 += __shfl_xor_sync(0xffffffffu, p0, o);
            p1 += __shfl_xor_sync(0xffffffffu, p1, o);
            p2 += __shfl_xor_sync(0xffffffffu, p2, o);
            p3 += __shfl_xor_sync(0xffffffffu, p3, o);
        }
        if (lane == 0) {
            float bj = e2rb[j];
            float ps[4] = {p0, p1, p2, p3};
#pragma unroll
            for (int st = 0; st < 4; st++) {
                float sn, cn; sincosf(0.5f * (ps[st] + bj), &sn, &cn);
                g_cs[(s0 + st) * 64 + j] = make_float2(cn, sn);
            }
        }
    }
    if (blockIdx.x == 0 && wid == 0) {
        float re = 0.f, im = 0.f, a = 0.f;
        if (lane < 16) { re = mix[2 * lane]; im = mix[2 * lane + 1]; a = sqrtf(re * re + im * im); }
        float s = a;
#pragma unroll
        for (int o = 16; o; o >>= 1) s += __shfl_xor_sync(0xffffffffu, s, o);
        s = fmaxf(s, 1e-12f);
        if (lane < 16) g_coeffs[lane] = make_float2(re / s, im / s);
    }
    if (blockIdx.x == 0 && wid == 1) {
        float sn, cn; sincosf(0.5f * qff[lane], &sn, &cn);
        g_qcs[lane] = make_float2(cn, sn);
    }
}

// =============================================================================
// k_quantum: grid 16 (batch), 512 thr (16 warps = 16 words). Fuses:
// 3x (sim14 + word reduction + poly accum) + normalize + qff sim + measure + ff1
// =============================================================================
__global__ void __launch_bounds__(512) k_quantum(
    const float* __restrict__ poly, const float* __restrict__ ff1W,
    const float* __restrict__ ff1b) {
    __shared__ float2 cs_sh[16 * 64];   // 8 KB
    __shared__ float2 stw[16][256];     // 32 KB  [w][r*32+lane]
    __shared__ float2 work[256];        // 2 KB
    __shared__ float2 accs[256];        // 2 KB
    __shared__ float2 qcs[32];
    __shared__ float2 coef[16];
    __shared__ float  rsum[8];
    __shared__ float  ex[24];

    int tid = threadIdx.x, b = blockIdx.x;
    int w = tid >> 5, lane = tid & 31;

    for (int i = tid; i < 1024; i += 512) cs_sh[i] = g_cs[b * 1024 + i];
    if (tid < 32) qcs[tid] = g_qcs[tid];
    if (tid < 16) coef[tid] = g_coeffs[tid];
    __syncthreads();

    float2 st[8];
#pragma unroll 1
    for (int d = 1; d <= 3; d++) {
        if (d == 1) {
#pragma unroll
            for (int r = 0; r < 8; r++)
                st[r] = make_float2((lane == 0 && r == 0) ? 1.f : 0.f, 0.f);
        } else {
#pragma unroll
            for (int r = 0; r < 8; r++) st[r] = work[r * 32 + lane];
        }
        sim_layer(st, cs_sh + w * 64, lane);
        sim_layer(st, cs_sh + w * 64 + 32, lane);
#pragma unroll
        for (int r = 0; r < 8; r++) stw[w][r * 32 + lane] = st[r];
        __syncthreads();
        if (tid < 256) {
            float2 rd = make_float2(0.f, 0.f);
#pragma unroll
            for (int ww = 0; ww < 16; ww++) {
                float2 c = coef[ww];
                float2 s = stw[ww][tid];
                rd.x = fmaf(s.x, c.x, fmaf(-s.y, c.y, rd.x));
                rd.y = fmaf(s.x, c.y, fmaf(s.y, c.x, rd.y));
            }
            work[tid] = rd;
            float pd = poly[d];
            if (d == 1) {
                accs[tid] = make_float2(pd * rd.x + (tid == 0 ? poly[0] : 0.f), pd * rd.y);
            } else {
                float2 a = accs[tid];
                accs[tid] = make_float2(fmaf(pd, rd.x, a.x), fmaf(pd, rd.y, a.y));
            }
        }
        __syncthreads();
    }

    // normalize (first 8 warps hold the 256 amps)
    float invp = 1.f / (fabsf(poly[0]) + fabsf(poly[1]) + fabsf(poly[2]) + fabsf(poly[3]));
    float pn = 0.f;
    float2 v = make_float2(0.f, 0.f);
    if (tid < 256) {
        float2 a = accs[tid];
        v = make_float2(a.x * invp, a.y * invp);
        pn = v.x * v.x + v.y * v.y;
    }
#pragma unroll
    for (int o = 16; o; o >>= 1) pn += __shfl_xor_sync(0xffffffffu, pn, o);
    if (tid < 256 && lane == 0) rsum[w] = pn;
    __syncthreads();
    float tot = rsum[0] + rsum[1] + rsum[2] + rsum[3] +
                rsum[4] + rsum[5] + rsum[6] + rsum[7];
    float fp = sqrtf(tot);
    if (tid == 0) g_fp[b] = fp;
    float inv = 1.f / fmaxf(fp, 1e-12f);
    if (tid < 256) work[tid] = make_float2(v.x * inv, v.y * inv);
    __syncthreads();

    // qff sim + measure on warp 0
    if (w == 0) {
#pragma unroll
        for (int r = 0; r < 8; r++) st[r] = work[r * 32 + lane];
        sim_layer(st, qcs, lane);

#define MEAS_REG(W_) { constexpr int m = 1 << (7 - (W_)); \
        float cr = 0.f, ci = 0.f, zz = 0.f; \
        _Pragma("unroll") \
        for (int r = 0; r < 8; r++) if (!(r & m)) { \
            float2 a0 = st[r], a1 = st[r | m]; \
            cr += a0.x * a1.x + a0.y * a1.y; \
            ci += a0.x * a1.y - a0.y * a1.x; \
            zz += a0.x * a0.x + a0.y * a0.y - a1.x * a1.x - a1.y * a1.y; } \
        _Pragma("unroll") \
        for (int o = 16; o; o >>= 1) { \
            cr += __shfl_xor_sync(0xffffffffu, cr, o); \
            ci += __shfl_xor_sync(0xffffffffu, ci, o); \
            zz += __shfl_xor_sync(0xffffffffu, zz, o); } \
        if (lane == 0) { ex[(W_)] = 2.f * cr; ex[8 + (W_)] = 2.f * ci; ex[16 + (W_)] = zz; } }

#define MEAS_LANE(W_) { constexpr int lm = 1 << (4 - (W_)); \
        bool hi = (lane & lm) != 0; \
        float cr = 0.f, ci = 0.f, zz = 0.f; \
        _Pragma("unroll") \
        for (int r = 0; r < 8; r++) { \
            float px = __shfl_xor_sync(0xffffffffu, st[r].x, lm); \
            float py = __shfl_xor_sync(0xffffffffu, st[r].y, lm); \
            float n2 = st[r].x * st[r].x + st[r].y * st[r].y; \
            if (!hi) { cr += st[r].x * px + st[r].y * py; \
                       ci += st[r].x * py - st[r].y * px; zz += n2; } \
            else zz -= n2; } \
        _Pragma("unroll") \
        for (int o = 16; o; o >>= 1) { \
            cr += __shfl_xor_sync(0xffffffffu, cr, o); \
            ci += __shfl_xor_sync(0xffffffffu, ci, o); \
            zz += __shfl_xor_sync(0xffffffffu, zz, o); } \
        if (lane == 0) { ex[(W_)] = 2.f * cr; ex[8 + (W_)] = 2.f * ci; ex[16 + (W_)] = zz; } }

        MEAS_LANE(0); MEAS_LANE(1); MEAS_LANE(2); MEAS_LANE(3); MEAS_LANE(4);
        MEAS_REG(5);  MEAS_REG(6);  MEAS_REG(7);
    }
    __syncthreads();

    // ff1: one output per thread
    {
        int j = tid;
        float h = ff1b[j];
        const float* wr = ff1W + j * 24;
#pragma unroll
        for (int m = 0; m < 24; m++) h = fmaf(ex[m], wr[m], h);
        h = fmaxf(h, 0.f);
        ((float*)&g_hp[j * 8 + (b >> 1)])[b & 1] = h;
    }
}

// =============================================================================
// k_ff2: 148 blocks x 256 thr (1 block/SM, 255-reg cap), 340 rows/block,
// cp.async double-buffered W2 staging, f32x2 batch-packed accumulators.
// =============================================================================
#define FF2_ROWS   340
#define FF2_STRIDE 36
#define FF2_BUF    (FF2_ROWS * FF2_STRIDE)
#define FF2_SMEM   (32768 + 2 * FF2_BUF * 4)

__device__ __forceinline__ void ff2_stage(float* buf, const float* __restrict__ W2,
                                          int base, int k0, int tid) {
    uint32_t sb = (uint32_t)__cvta_generic_to_shared(buf);
#pragma unroll 1
    for (int u = tid; u < FF2_ROWS * 8; u += 256) {
        int rr = u >> 3, q = u & 7;
        int v = base + rr; if (v >= VQ) v = VQ - 1;
        cp16(sb + (uint32_t)(rr * FF2_STRIDE + q * 4) * 4,
             W2 + (size_t)v * EMBQ + k0 + q * 4);
    }
}

__global__ void __launch_bounds__(256, 1) k_ff2(const float* __restrict__ W2,
                                                const float* __restrict__ b2,
                                                float* __restrict__ out, int out_size) {
    extern __shared__ char dsm[];
    ull*   hsh = (ull*)dsm;                          // 32 KB
    float* sW0 = (float*)(dsm + 32768);
    float* sW1 = sW0 + FF2_BUF;
    const ulonglong2* hsh2 = (const ulonglong2*)hsh;

    int t = threadIdx.x;
    int base = blockIdx.x * FF2_ROWS;
    bool has2 = (256 + t) < FF2_ROWS;

    for (int i = t; i < 4096; i += 256) hsh[i] = g_hp[i];

    ff2_stage(sW0, W2, base, 0, t);
    asm volatile("cp.async.commit_group;");

    ull acc0[8], acc1[8];
#pragma unroll
    for (int bp = 0; bp < 8; bp++) { acc0[bp] = 0ull; acc1[bp] = 0ull; }

#pragma unroll 1
    for (int c = 0; c < 16; c++) {
        if (c < 15) {
            ff2_stage((c & 1) ? sW0 : sW1, W2, base, (c + 1) * 32, t);
            asm volatile("cp.async.commit_group;");
            asm volatile("cp.async.wait_group 1;");
        } else {
            asm volatile("cp.async.wait_group 0;");
        }
        __syncthreads();
        const float4* b4 = (const float4*)((c & 1) ? sW1 : sW0);
        int k0 = c * 32;
#pragma unroll 1
        for (int q = 0; q < 8; q++) {
            float4 wA = b4[t * 9 + q];
            float4 wB = make_float4(0.f, 0.f, 0.f, 0.f);
            if (has2) wB = b4[(256 + t) * 9 + q];
            float wa[4] = {wA.x, wA.y, wA.z, wA.w};
            float wb[4] = {wB.x, wB.y, wB.z, wB.w};
            const ulonglong2* hp = hsh2 + (size_t)(k0 + q * 4) * 4;
#pragma unroll
            for (int j = 0; j < 4; j++) {
                ulonglong2 h01 = hp[j * 4 + 0], h23 = hp[j * 4 + 1];
                ulonglong2 h45 = hp[j * 4 + 2], h67 = hp[j * 4 + 3];
                ull WA = dup2(wa[j]);
                ffma2(acc0[0], h01.x, WA); ffma2(acc0[1], h01.y, WA);
                ffma2(acc0[2], h23.x, WA); ffma2(acc0[3], h23.y, WA);
                ffma2(acc0[4], h45.x, WA); ffma2(acc0[5], h45.y, WA);
                ffma2(acc0[6], h67.x, WA); ffma2(acc0[7], h67.y, WA);
                if (has2) {
                    ull WB = dup2(wb[j]);
                    ffma2(acc1[0], h01.x, WB); ffma2(acc1[1], h01.y, WB);
                    ffma2(acc1[2], h23.x, WB); ffma2(acc1[3], h23.y, WB);
                    ffma2(acc1[4], h45.x, WB); ffma2(acc1[5], h45.y, WB);
                    ffma2(acc1[6], h67.x, WB); ffma2(acc1[7], h67.y, WB);
                }
            }
        }
        __syncthreads();
    }

    int r0 = base + t;
    if (r0 < VQ) {
        float bias = b2[r0];
#pragma unroll
        for (int bp = 0; bp < 8; bp++) {
            float lo, hi; unpack2(acc0[bp], lo, hi);
            out[(size_t)(2 * bp) * VQ + r0]     = lo + bias;
            out[(size_t)(2 * bp + 1) * VQ + r0] = hi + bias;
        }
    }
    int r1 = base + 256 + t;
    if (has2 && r1 < VQ) {
        float bias = b2[r1];
#pragma unroll
        for (int bp = 0; bp < 8; bp++) {
            float lo, hi; unpack2(acc1[bp], lo, hi);
            out[(size_t)(2 * bp) * VQ + r1]     = lo + bias;
            out[(size_t)(2 * bp + 1) * VQ + r1] = hi + bias;
        }
    }
    if (blockIdx.x == 0 && t == 0 && out_size > 16 * VQ) {
        float s = 0.f;
        for (int b = 0; b < 16; b++) s += g_fp[b];
        out[16 * VQ] = s * (1.f / 16.f);
    }
}

// ------------------------------ launch ---------------------------------------
extern "C" void kernel_launch(void* const* d_in, const int* in_sizes, int n_in,
                              void* d_out, int out_size) {
    const int*   x    = (const int*)  d_in[0];
    const float* embW = (const float*)d_in[1];
    const float* e2rW = (const float*)d_in[2];
    const float* e2rb = (const float*)d_in[3];
    const float* poly = (const float*)d_in[4];
    const float* mix  = (const float*)d_in[5];
    const float* qff  = (const float*)d_in[6];
    const float* ff1W = (const float*)d_in[7];
    const float* ff1b = (const float*)d_in[8];
    const float* W2   = (const float*)d_in[9];
    const float* b2   = (const float*)d_in[10];
    float* out = (float*)d_out;

    static bool attr_set = false;
    if (!attr_set) {
        cudaFuncSetAttribute(k_ff2, cudaFuncAttributeMaxDynamicSharedMemorySize, FF2_SMEM);
        attr_set = true;
    }

    k_emb<<<64, 256>>>(x, embW, e2rW, e2rb, mix, qff);
    k_quantum<<<16, 512>>>(poly, ff1W, ff1b);
    k_ff2<<<148, 256, FF2_SMEM>>>(W2, b2, out, out_size);
}

// round 12
// speedup vs baseline: 1.8184x; 1.2534x over previous
#include <cuda_runtime.h>
#include <cuda_bf16.h>
#include <cstdint>

#define VQ   50257
#define EMBQ 512
typedef unsigned long long ull;

// ------------------------------ scratch -------------------------------------
__device__ float2 g_cs[256 * 64];   // per (b,w) gate (cos(th/2), sin(th/2))
__device__ float2 g_qcs[32];        // qff gate table
__device__ float2 g_coeffs[16];     // normalized mix coefficients
__device__ float  g_fp[16];         // final_probs
__device__ ull    g_hp[512 * 8];    // h packed: [k*8+bp] = f32x2(h[2bp][k], h[2bp+1][k])

// ------------------------------ f32x2 helpers --------------------------------
__device__ __forceinline__ ull dup2(float a) {
    ull r; asm("mov.b64 %0, {%1, %1};" : "=l"(r) : "f"(a)); return r;
}
__device__ __forceinline__ void ffma2(ull& d, ull a, ull b) {
    asm("fma.rn.f32x2 %0, %1, %2, %0;" : "+l"(d) : "l"(a), "l"(b));
}
__device__ __forceinline__ void unpack2(ull v, float& lo, float& hi) {
    asm("mov.b64 {%0, %1}, %2;" : "=f"(lo), "=f"(hi) : "l"(v));
}
__device__ __forceinline__ void cp16(uint32_t dst, const void* src) {
    asm volatile("cp.async.cg.shared.global [%0], [%1], 16;" :: "r"(dst), "l"(src));
}

// =============================================================================
// Warp-resident 8-qubit sim. Amp index i: lane = i>>3 (bits 7..3), r = i&7.
// Qubit w <-> bit (7-w): w<=4 -> lane bit (1<<(4-w)); w>=5 -> reg bit (1<<(7-w)).
// =============================================================================
template <int W>
__device__ __forceinline__ void ry_t(float2 st[8], float2 g, int lane) {
    const float c = g.x, s = g.y;
    if constexpr (W >= 5) {
        constexpr int m = 1 << (7 - W);
#pragma unroll
        for (int r = 0; r < 8; r++) if (!(r & m)) {
            float2 a0 = st[r], a1 = st[r | m];
            st[r]     = make_float2(c * a0.x - s * a1.x, c * a0.y - s * a1.y);
            st[r | m] = make_float2(s * a0.x + c * a1.x, s * a0.y + c * a1.y);
        }
    } else {
        constexpr int lm = 1 << (4 - W);
        const float sg = (lane & lm) ? s : -s;
#pragma unroll
        for (int r = 0; r < 8; r++) {
            float px = __shfl_xor_sync(0xffffffffu, st[r].x, lm);
            float py = __shfl_xor_sync(0xffffffffu, st[r].y, lm);
            st[r].x = fmaf(sg, px, c * st[r].x);
            st[r].y = fmaf(sg, py, c * st[r].y);
        }
    }
}

// CRX (control bit==1): new = c*mine + s*(partner.y, -partner.x)
template <int C, int T>
__device__ __forceinline__ void crx_t(float2 st[8], float2 g, int lane) {
    const float c = g.x, s = g.y;
    if constexpr (C >= 5) {
        constexpr int cm = 1 << (7 - C);
        if constexpr (T >= 5) {
            constexpr int tm = 1 << (7 - T);
#pragma unroll
            for (int r = 0; r < 8; r++) if ((r & cm) && !(r & tm)) {
                float2 a0 = st[r], a1 = st[r | tm];
                st[r]      = make_float2(c * a0.x + s * a1.y, c * a0.y - s * a1.x);
                st[r | tm] = make_float2(c * a1.x + s * a0.y, c * a1.y - s * a0.x);
            }
        } else {
            constexpr int tlm = 1 << (4 - T);
#pragma unroll
            for (int r = 0; r < 8; r++) {
                float px = __shfl_xor_sync(0xffffffffu, st[r].x, tlm);
                float py = __shfl_xor_sync(0xffffffffu, st[r].y, tlm);
                if (r & cm) {
                    st[r].x = fmaf(s, py, c * st[r].x);
                    st[r].y = fmaf(-s, px, c * st[r].y);
                }
            }
        }
    } else {
        constexpr int clm = 1 << (4 - C);
        const bool act = (lane & clm) != 0;
        if constexpr (T >= 5) {
            constexpr int tm = 1 << (7 - T);
#pragma unroll
            for (int r = 0; r < 8; r++) if (!(r & tm)) {
                float2 a0 = st[r], a1 = st[r | tm];
                if (act) {
                    st[r]      = make_float2(c * a0.x + s * a1.y, c * a0.y - s * a1.x);
                    st[r | tm] = make_float2(c * a1.x + s * a0.y, c * a1.y - s * a0.x);
                }
            }
        } else {
            constexpr int tlm = 1 << (4 - T);
#pragma unroll
            for (int r = 0; r < 8; r++) {
                float px = __shfl_xor_sync(0xffffffffu, st[r].x, tlm);
                float py = __shfl_xor_sync(0xffffffffu, st[r].y, tlm);
                if (act) {
                    st[r].x = fmaf(s, py, c * st[r].x);
                    st[r].y = fmaf(-s, px, c * st[r].y);
                }
            }
        }
    }
}

__device__ __forceinline__ void sim_layer(float2 st[8], const float2* cs, int lane) {
    int k = 0;
    ry_t<0>(st, cs[k++], lane); ry_t<1>(st, cs[k++], lane); ry_t<2>(st, cs[k++], lane);
    ry_t<3>(st, cs[k++], lane); ry_t<4>(st, cs[k++], lane); ry_t<5>(st, cs[k++], lane);
    ry_t<6>(st, cs[k++], lane); ry_t<7>(st, cs[k++], lane);
    crx_t<7,0>(st, cs[k++], lane); crx_t<6,7>(st, cs[k++], lane); crx_t<5,6>(st, cs[k++], lane);
    crx_t<4,5>(st, cs[k++], lane); crx_t<3,4>(st, cs[k++], lane); crx_t<2,3>(st, cs[k++], lane);
    crx_t<1,2>(st, cs[k++], lane); crx_t<0,1>(st, cs[k++], lane);
    ry_t<0>(st, cs[k++], lane); ry_t<1>(st, cs[k++], lane); ry_t<2>(st, cs[k++], lane);
    ry_t<3>(st, cs[k++], lane); ry_t<4>(st, cs[k++], lane); ry_t<5>(st, cs[k++], lane);
    ry_t<6>(st, cs[k++], lane); ry_t<7>(st, cs[k++], lane);
    crx_t<7,6>(st, cs[k++], lane); crx_t<0,7>(st, cs[k++], lane); crx_t<1,0>(st, cs[k++], lane);
    crx_t<2,1>(st, cs[k++], lane); crx_t<3,2>(st, cs[k++], lane); crx_t<4,3>(st, cs[k++], lane);
    crx_t<5,4>(st, cs[k++], lane); crx_t<6,5>(st, cs[k++], lane);
}

// =============================================================================
// k_emb: grid (64, 8): x = state group (4 states), y = j-group (8 rotations).
// 256 thr = 8 warps; warp w computes j = jg*8+w for all 4 states.
// =============================================================================
__global__ void __launch_bounds__(256) k_emb(
    const int* __restrict__ x, const float* __restrict__ embW,
    const float* __restrict__ e2rW, const float* __restrict__ e2rb,
    const float* __restrict__ mix, const float* __restrict__ qff) {
    __shared__ float emb[4][EMBQ];
    __shared__ int sx[4];
    int tid = threadIdx.x, s0 = blockIdx.x * 4, jg = blockIdx.y;
    if (tid < 4) sx[tid] = x[s0 + tid];
    __syncthreads();
    for (int u = tid; u < 512; u += 256) {           // 4 rows x 128 float4
        int strow = u >> 7, c4 = u & 127;
        ((float4*)emb[strow])[c4] =
            ((const float4*)(embW + (size_t)sx[strow] * EMBQ))[c4];
    }
    __syncthreads();
    int wid = tid >> 5, lane = tid & 31;
    int j = jg * 8 + wid;
    float p0 = 0.f, p1 = 0.f, p2 = 0.f, p3 = 0.f;
    const float* wr = e2rW + (size_t)j * EMBQ;
#pragma unroll
    for (int k = lane; k < EMBQ; k += 32) {
        float wv = wr[k];
        p0 = fmaf(emb[0][k], wv, p0); p1 = fmaf(emb[1][k], wv, p1);
        p2 = fmaf(emb[2][k], wv, p2); p3 = fmaf(emb[3][k], wv, p3);
    }
#pragma unroll
    for (int o = 16; o; o >>= 1) {
        p0 += __shfl_xor_sync(0xffffffffu, p0, o);
        p1 += __shfl_xor_sync(0xffffffffu, p1, o);
        p2 += __shfl_xor_sync(0xffffffffu, p2, o);
        p3 += __shfl_xor_sync(0xffffffffu, p3, o);
    }
    if (lane < 4) {
        float pv = (lane == 0) ? p0 : (lane == 1) ? p1 : (lane == 2) ? p2 : p3;
        float sn, cn; sincosf(0.5f * (pv + e2rb[j]), &sn, &cn);
        g_cs[(s0 + lane) * 64 + j] = make_float2(cn, sn);
    }
    if (blockIdx.x == 0 && jg == 0 && wid == 0) {
        float re = 0.f, im = 0.f, a = 0.f;
        if (lane < 16) { re = mix[2 * lane]; im = mix[2 * lane + 1]; a = sqrtf(re * re + im * im); }
        float s = a;
#pragma unroll
        for (int o = 16; o; o >>= 1) s += __shfl_xor_sync(0xffffffffu, s, o);
        s = fmaxf(s, 1e-12f);
        if (lane < 16) g_coeffs[lane] = make_float2(re / s, im / s);
    }
    if (blockIdx.x == 0 && jg == 0 && wid == 1) {
        float sn, cn; sincosf(0.5f * qff[lane], &sn, &cn);
        g_qcs[lane] = make_float2(cn, sn);
    }
}

// =============================================================================
// k_quantum: grid 16 (batch), 512 thr (16 warps = 16 words). Fuses:
// 3x (sim14 + word reduction + poly accum) + normalize + qff sim + measure + ff1
// =============================================================================
__global__ void __launch_bounds__(512) k_quantum(
    const float* __restrict__ poly, const float* __restrict__ ff1W,
    const float* __restrict__ ff1b) {
    __shared__ float2 cs_sh[16 * 64];
    __shared__ float2 stw[16][256];
    __shared__ float2 work[256];
    __shared__ float2 accs[256];
    __shared__ float2 qcs[32];
    __shared__ float2 coef[16];
    __shared__ float  rsum[8];
    __shared__ float  ex[24];

    int tid = threadIdx.x, b = blockIdx.x;
    int w = tid >> 5, lane = tid & 31;

    for (int i = tid; i < 1024; i += 512) cs_sh[i] = g_cs[b * 1024 + i];
    if (tid < 32) qcs[tid] = g_qcs[tid];
    if (tid < 16) coef[tid] = g_coeffs[tid];
    __syncthreads();

    float2 st[8];
#pragma unroll 1
    for (int d = 1; d <= 3; d++) {
        if (d == 1) {
#pragma unroll
            for (int r = 0; r < 8; r++)
                st[r] = make_float2((lane == 0 && r == 0) ? 1.f : 0.f, 0.f);
        } else {
#pragma unroll
            for (int r = 0; r < 8; r++) st[r] = work[r * 32 + lane];
        }
        sim_layer(st, cs_sh + w * 64, lane);
        sim_layer(st, cs_sh + w * 64 + 32, lane);
#pragma unroll
        for (int r = 0; r < 8; r++) stw[w][r * 32 + lane] = st[r];
        __syncthreads();
        if (tid < 256) {
            float2 rd = make_float2(0.f, 0.f);
#pragma unroll
            for (int ww = 0; ww < 16; ww++) {
                float2 c = coef[ww];
                float2 s = stw[ww][tid];
                rd.x = fmaf(s.x, c.x, fmaf(-s.y, c.y, rd.x));
                rd.y = fmaf(s.x, c.y, fmaf(s.y, c.x, rd.y));
            }
            work[tid] = rd;
            float pd = poly[d];
            if (d == 1) {
                accs[tid] = make_float2(pd * rd.x + (tid == 0 ? poly[0] : 0.f), pd * rd.y);
            } else {
                float2 a = accs[tid];
                accs[tid] = make_float2(fmaf(pd, rd.x, a.x), fmaf(pd, rd.y, a.y));
            }
        }
        __syncthreads();
    }

    float invp = 1.f / (fabsf(poly[0]) + fabsf(poly[1]) + fabsf(poly[2]) + fabsf(poly[3]));
    float pn = 0.f;
    float2 v = make_float2(0.f, 0.f);
    if (tid < 256) {
        float2 a = accs[tid];
        v = make_float2(a.x * invp, a.y * invp);
        pn = v.x * v.x + v.y * v.y;
    }
#pragma unroll
    for (int o = 16; o; o >>= 1) pn += __shfl_xor_sync(0xffffffffu, pn, o);
    if (tid < 256 && lane == 0) rsum[w] = pn;
    __syncthreads();
    float tot = rsum[0] + rsum[1] + rsum[2] + rsum[3] +
                rsum[4] + rsum[5] + rsum[6] + rsum[7];
    float fp = sqrtf(tot);
    if (tid == 0) g_fp[b] = fp;
    float inv = 1.f / fmaxf(fp, 1e-12f);
    if (tid < 256) work[tid] = make_float2(v.x * inv, v.y * inv);
    __syncthreads();

    if (w == 0) {
#pragma unroll
        for (int r = 0; r < 8; r++) st[r] = work[r * 32 + lane];
        sim_layer(st, qcs, lane);

#define MEAS_REG(W_) { constexpr int m = 1 << (7 - (W_)); \
        float cr = 0.f, ci = 0.f, zz = 0.f; \
        _Pragma("unroll") \
        for (int r = 0; r < 8; r++) if (!(r & m)) { \
            float2 a0 = st[r], a1 = st[r | m]; \
            cr += a0.x * a1.x + a0.y * a1.y; \
            ci += a0.x * a1.y - a0.y * a1.x; \
            zz += a0.x * a0.x + a0.y * a0.y - a1.x * a1.x - a1.y * a1.y; } \
        _Pragma("unroll") \
        for (int o = 16; o; o >>= 1) { \
            cr += __shfl_xor_sync(0xffffffffu, cr, o); \
            ci += __shfl_xor_sync(0xffffffffu, ci, o); \
            zz += __shfl_xor_sync(0xffffffffu, zz, o); } \
        if (lane == 0) { ex[(W_)] = 2.f * cr; ex[8 + (W_)] = 2.f * ci; ex[16 + (W_)] = zz; } }

#define MEAS_LANE(W_) { constexpr int lm = 1 << (4 - (W_)); \
        bool hi = (lane & lm) != 0; \
        float cr = 0.f, ci = 0.f, zz = 0.f; \
        _Pragma("unroll") \
        for (int r = 0; r < 8; r++) { \
            float px = __shfl_xor_sync(0xffffffffu, st[r].x, lm); \
            float py = __shfl_xor_sync(0xffffffffu, st[r].y, lm); \
            float n2 = st[r].x * st[r].x + st[r].y * st[r].y; \
            if (!hi) { cr += st[r].x * px + st[r].y * py; \
                       ci += st[r].x * py - st[r].y * px; zz += n2; } \
            else zz -= n2; } \
        _Pragma("unroll") \
        for (int o = 16; o; o >>= 1) { \
            cr += __shfl_xor_sync(0xffffffffu, cr, o); \
            ci += __shfl_xor_sync(0xffffffffu, ci, o); \
            zz += __shfl_xor_sync(0xffffffffu, zz, o); } \
        if (lane == 0) { ex[(W_)] = 2.f * cr; ex[8 + (W_)] = 2.f * ci; ex[16 + (W_)] = zz; } }

        MEAS_LANE(0); MEAS_LANE(1); MEAS_LANE(2); MEAS_LANE(3); MEAS_LANE(4);
        MEAS_REG(5);  MEAS_REG(6);  MEAS_REG(7);
    }
    __syncthreads();

    {
        int j = tid;
        float h = ff1b[j];
        const float* wr = ff1W + j * 24;
#pragma unroll
        for (int m = 0; m < 24; m++) h = fmaf(ex[m], wr[m], h);
        h = fmaxf(h, 0.f);
        ((float*)&g_hp[j * 8 + (b >> 1)])[b & 1] = h;
    }
}

// =============================================================================
// k_ff2: 148 blocks x 256 thr (1 block/SM), 340 rows/block, cp.async
// double-buffered, f32x2 batch-packed accumulators, deep ILP in q-loop.
// =============================================================================
#define FF2_ROWS   340
#define FF2_STRIDE 36
#define FF2_BUF    (FF2_ROWS * FF2_STRIDE)
#define FF2_SMEM   (32768 + 2 * FF2_BUF * 4)

__device__ __forceinline__ void ff2_stage(float* buf, const float* __restrict__ W2,
                                          int base, int k0, int tid) {
    uint32_t sb = (uint32_t)__cvta_generic_to_shared(buf);
#pragma unroll 1
    for (int u = tid; u < FF2_ROWS * 8; u += 256) {
        int rr = u >> 3, q = u & 7;
        int v = base + rr; if (v >= VQ) v = VQ - 1;
        cp16(sb + (uint32_t)(rr * FF2_STRIDE + q * 4) * 4,
             W2 + (size_t)v * EMBQ + k0 + q * 4);
    }
}

__global__ void __launch_bounds__(256, 1) k_ff2(const float* __restrict__ W2,
                                                const float* __restrict__ b2,
                                                float* __restrict__ out, int out_size) {
    extern __shared__ char dsm[];
    ull*   hsh = (ull*)dsm;                          // 32 KB
    float* sW0 = (float*)(dsm + 32768);
    float* sW1 = sW0 + FF2_BUF;
    const ulonglong2* hsh2 = (const ulonglong2*)hsh;

    int t = threadIdx.x;
    int base = blockIdx.x * FF2_ROWS;
    bool has2 = (256 + t) < FF2_ROWS;

    for (int i = t; i < 4096; i += 256) hsh[i] = g_hp[i];

    ff2_stage(sW0, W2, base, 0, t);
    asm volatile("cp.async.commit_group;");

    ull acc0[8], acc1[8];
#pragma unroll
    for (int bp = 0; bp < 8; bp++) { acc0[bp] = 0ull; acc1[bp] = 0ull; }

#pragma unroll 1
    for (int c = 0; c < 16; c++) {
        if (c < 15) {
            ff2_stage((c & 1) ? sW0 : sW1, W2, base, (c + 1) * 32, t);
            asm volatile("cp.async.commit_group;");
            asm volatile("cp.async.wait_group 1;");
        } else {
            asm volatile("cp.async.wait_group 0;");
        }
        __syncthreads();
        const float4* b4 = (const float4*)((c & 1) ? sW1 : sW0);
        const ulonglong2* hpc = hsh2 + (size_t)(c * 32) * 4;
#pragma unroll 4
        for (int q = 0; q < 8; q++) {
            float4 wA = b4[t * 9 + q];
            float4 wB = make_float4(0.f, 0.f, 0.f, 0.f);
            if (has2) wB = b4[(256 + t) * 9 + q];
            float wa[4] = {wA.x, wA.y, wA.z, wA.w};
            float wb[4] = {wB.x, wB.y, wB.z, wB.w};
            const ulonglong2* hq = hpc + q * 16;
#pragma unroll
            for (int j = 0; j < 4; j++) {
                ulonglong2 h01 = hq[j * 4 + 0], h23 = hq[j * 4 + 1];
                ulonglong2 h45 = hq[j * 4 + 2], h67 = hq[j * 4 + 3];
                ull WA = dup2(wa[j]);
                ffma2(acc0[0], h01.x, WA); ffma2(acc0[1], h01.y, WA);
                ffma2(acc0[2], h23.x, WA); ffma2(acc0[3], h23.y, WA);
                ffma2(acc0[4], h45.x, WA); ffma2(acc0[5], h45.y, WA);
                ffma2(acc0[6], h67.x, WA); ffma2(acc0[7], h67.y, WA);
                if (has2) {
                    ull WB = dup2(wb[j]);
                    ffma2(acc1[0], h01.x, WB); ffma2(acc1[1], h01.y, WB);
                    ffma2(acc1[2], h23.x, WB); ffma2(acc1[3], h23.y, WB);
                    ffma2(acc1[4], h45.x, WB); ffma2(acc1[5], h45.y, WB);
                    ffma2(acc1[6], h67.x, WB); ffma2(acc1[7], h67.y, WB);
                }
            }
        }
        __syncthreads();
    }

    int r0 = base + t;
    if (r0 < VQ) {
        float bias = b2[r0];
#pragma unroll
        for (int bp = 0; bp < 8; bp++) {
            float lo, hi; unpack2(acc0[bp], lo, hi);
            out[(size_t)(2 * bp) * VQ + r0]     = lo + bias;
            out[(size_t)(2 * bp + 1) * VQ + r0] = hi + bias;
        }
    }
    int r1 = base + 256 + t;
    if (has2 && r1 < VQ) {
        float bias = b2[r1];
#pragma unroll
        for (int bp = 0; bp < 8; bp++) {
            float lo, hi; unpack2(acc1[bp], lo, hi);
            out[(size_t)(2 * bp) * VQ + r1]     = lo + bias;
            out[(size_t)(2 * bp + 1) * VQ + r1] = hi + bias;
        }
    }
    if (blockIdx.x == 0 && t == 0 && out_size > 16 * VQ) {
        float s = 0.f;
        for (int b = 0; b < 16; b++) s += g_fp[b];
        out[16 * VQ] = s * (1.f / 16.f);
    }
}

// ------------------------------ launch ---------------------------------------
extern "C" void kernel_launch(void* const* d_in, const int* in_sizes, int n_in,
                              void* d_out, int out_size) {
    const int*   x    = (const int*)  d_in[0];
    const float* embW = (const float*)d_in[1];
    const float* e2rW = (const float*)d_in[2];
    const float* e2rb = (const float*)d_in[3];
    const float* poly = (const float*)d_in[4];
    const float* mix  = (const float*)d_in[5];
    const float* qff  = (const float*)d_in[6];
    const float* ff1W = (const float*)d_in[7];
    const float* ff1b = (const float*)d_in[8];
    const float* W2   = (const float*)d_in[9];
    const float* b2   = (const float*)d_in[10];
    float* out = (float*)d_out;

    cudaFuncSetAttribute(k_ff2, cudaFuncAttributeMaxDynamicSharedMemorySize, FF2_SMEM);

    dim3 eg(64, 8);
    k_emb<<<eg, 256>>>(x, embW, e2rW, e2rb, mix, qff);
    k_quantum<<<16, 512>>>(poly, ff1W, ff1b);
    k_ff2<<<148, 256, FF2_SMEM>>>(W2, b2, out, out_size);
}

// round 16
// speedup vs baseline: 2.1886x; 1.2036x over previous
#include <cuda_runtime.h>
#include <cuda_bf16.h>
#include <cstdint>

#define VQ   50257
#define EMBQ 512
typedef unsigned long long ull;

// ------------------------------ scratch -------------------------------------
__device__ float2 g_cs[256 * 64];   // per (b,w) gate (cos(th/2), sin(th/2))
__device__ float2 g_qcs[32];        // qff gate table
__device__ float2 g_coeffs[16];     // normalized mix coefficients
__device__ float  g_fp[16];         // final_probs
__device__ float  g_ex[16 * 24];    // measured expectations per batch
__device__ ull    g_hp[512 * 8];    // h packed: [k*8+sl] = f32x2(h[2sl][k], h[2sl+1][k])

// ------------------------------ f32x2 helpers --------------------------------
__device__ __forceinline__ ull dup2(float a) {
    ull r; asm("mov.b64 %0, {%1, %1};" : "=l"(r) : "f"(a)); return r;
}
__device__ __forceinline__ void ffma2(ull& d, ull a, ull b) {
    asm("fma.rn.f32x2 %0, %1, %2, %0;" : "+l"(d) : "l"(a), "l"(b));
}
__device__ __forceinline__ void unpack2(ull v, float& lo, float& hi) {
    asm("mov.b64 {%0, %1}, %2;" : "=f"(lo), "=f"(hi) : "l"(v));
}
__device__ __forceinline__ void cp16(uint32_t dst, const void* src) {
    asm volatile("cp.async.cg.shared.global [%0], [%1], 16;" :: "r"(dst), "l"(src));
}

// =============================================================================
// Warp-resident 8-qubit sim. Amp index i: lane = i>>3, r = i&7.
// Qubit w <-> bit (7-w): w<=4 -> lane bit (1<<(4-w)); w>=5 -> reg bit (1<<(7-w)).
// =============================================================================
template <int W>
__device__ __forceinline__ void ry_t(float2 st[8], float2 g, int lane) {
    const float c = g.x, s = g.y;
    if constexpr (W >= 5) {
        constexpr int m = 1 << (7 - W);
#pragma unroll
        for (int r = 0; r < 8; r++) if (!(r & m)) {
            float2 a0 = st[r], a1 = st[r | m];
            st[r]     = make_float2(c * a0.x - s * a1.x, c * a0.y - s * a1.y);
            st[r | m] = make_float2(s * a0.x + c * a1.x, s * a0.y + c * a1.y);
        }
    } else {
        constexpr int lm = 1 << (4 - W);
        const float sg = (lane & lm) ? s : -s;
#pragma unroll
        for (int r = 0; r < 8; r++) {
            float px = __shfl_xor_sync(0xffffffffu, st[r].x, lm);
            float py = __shfl_xor_sync(0xffffffffu, st[r].y, lm);
            st[r].x = fmaf(sg, px, c * st[r].x);
            st[r].y = fmaf(sg, py, c * st[r].y);
        }
    }
}

template <int C, int T>
__device__ __forceinline__ void crx_t(float2 st[8], float2 g, int lane) {
    const float c = g.x, s = g.y;
    if constexpr (C >= 5) {
        constexpr int cm = 1 << (7 - C);
        if constexpr (T >= 5) {
            constexpr int tm = 1 << (7 - T);
#pragma unroll
            for (int r = 0; r < 8; r++) if ((r & cm) && !(r & tm)) {
                float2 a0 = st[r], a1 = st[r | tm];
                st[r]      = make_float2(c * a0.x + s * a1.y, c * a0.y - s * a1.x);
                st[r | tm] = make_float2(c * a1.x + s * a0.y, c * a1.y - s * a0.x);
            }
        } else {
            constexpr int tlm = 1 << (4 - T);
#pragma unroll
            for (int r = 0; r < 8; r++) {
                float px = __shfl_xor_sync(0xffffffffu, st[r].x, tlm);
                float py = __shfl_xor_sync(0xffffffffu, st[r].y, tlm);
                if (r & cm) {
                    st[r].x = fmaf(s, py, c * st[r].x);
                    st[r].y = fmaf(-s, px, c * st[r].y);
                }
            }
        }
    } else {
        constexpr int clm = 1 << (4 - C);
        const bool act = (lane & clm) != 0;
        if constexpr (T >= 5) {
            constexpr int tm = 1 << (7 - T);
#pragma unroll
            for (int r = 0; r < 8; r++) if (!(r & tm)) {
                float2 a0 = st[r], a1 = st[r | tm];
                if (act) {
                    st[r]      = make_float2(c * a0.x + s * a1.y, c * a0.y - s * a1.x);
                    st[r | tm] = make_float2(c * a1.x + s * a0.y, c * a1.y - s * a0.x);
                }
            }
        } else {
            constexpr int tlm = 1 << (4 - T);
#pragma unroll
            for (int r = 0; r < 8; r++) {
                float px = __shfl_xor_sync(0xffffffffu, st[r].x, tlm);
                float py = __shfl_xor_sync(0xffffffffu, st[r].y, tlm);
                if (act) {
                    st[r].x = fmaf(s, py, c * st[r].x);
                    st[r].y = fmaf(-s, px, c * st[r].y);
                }
            }
        }
    }
}

__device__ __forceinline__ void sim_layer(float2 st[8], const float2* cs, int lane) {
    int k = 0;
    ry_t<0>(st, cs[k++], lane); ry_t<1>(st, cs[k++], lane); ry_t<2>(st, cs[k++], lane);
    ry_t<3>(st, cs[k++], lane); ry_t<4>(st, cs[k++], lane); ry_t<5>(st, cs[k++], lane);
    ry_t<6>(st, cs[k++], lane); ry_t<7>(st, cs[k++], lane);
    crx_t<7,0>(st, cs[k++], lane); crx_t<6,7>(st, cs[k++], lane); crx_t<5,6>(st, cs[k++], lane);
    crx_t<4,5>(st, cs[k++], lane); crx_t<3,4>(st, cs[k++], lane); crx_t<2,3>(st, cs[k++], lane);
    crx_t<1,2>(st, cs[k++], lane); crx_t<0,1>(st, cs[k++], lane);
    ry_t<0>(st, cs[k++], lane); ry_t<1>(st, cs[k++], lane); ry_t<2>(st, cs[k++], lane);
    ry_t<3>(st, cs[k++], lane); ry_t<4>(st, cs[k++], lane); ry_t<5>(st, cs[k++], lane);
    ry_t<6>(st, cs[k++], lane); ry_t<7>(st, cs[k++], lane);
    crx_t<7,6>(st, cs[k++], lane); crx_t<0,7>(st, cs[k++], lane); crx_t<1,0>(st, cs[k++], lane);
    crx_t<2,1>(st, cs[k++], lane); crx_t<3,2>(st, cs[k++], lane); crx_t<4,3>(st, cs[k++], lane);
    crx_t<5,4>(st, cs[k++], lane); crx_t<6,5>(st, cs[k++], lane);
}

// =============================================================================
// k_emb: grid (64, 8): x = state group (4 states), y = j-group (8 rotations).
// float4 dot products, 4 independent LDG.128 per lane.
// =============================================================================
__global__ void __launch_bounds__(256) k_emb(
    const int* __restrict__ x, const float* __restrict__ embW,
    const float* __restrict__ e2rW, const float* __restrict__ e2rb,
    const float* __restrict__ mix, const float* __restrict__ qff) {
    __shared__ float emb[4][EMBQ];
    __shared__ int sx[4];
    int tid = threadIdx.x, s0 = blockIdx.x * 4, jg = blockIdx.y;
    if (tid < 4) sx[tid] = x[s0 + tid];
    __syncthreads();
    for (int u = tid; u < 512; u += 256) {
        int strow = u >> 7, c4 = u & 127;
        ((float4*)emb[strow])[c4] =
            ((const float4*)(embW + (size_t)sx[strow] * EMBQ))[c4];
    }
    __syncthreads();
    int wid = tid >> 5, lane = tid & 31;
    int j = jg * 8 + wid;
    float p0 = 0.f, p1 = 0.f, p2 = 0.f, p3 = 0.f;
    const float4* wr4 = (const float4*)(e2rW + (size_t)j * EMBQ);
    const float4* e0 = (const float4*)emb[0];
    const float4* e1 = (const float4*)emb[1];
    const float4* e2 = (const float4*)emb[2];
    const float4* e3 = (const float4*)emb[3];
#pragma unroll
    for (int it = 0; it < 4; it++) {
        int idx = lane + it * 32;
        float4 wv = wr4[idx];
        float4 a0 = e0[idx], a1 = e1[idx], a2 = e2[idx], a3 = e3[idx];
        p0 = fmaf(wv.x, a0.x, fmaf(wv.y, a0.y, fmaf(wv.z, a0.z, fmaf(wv.w, a0.w, p0))));
        p1 = fmaf(wv.x, a1.x, fmaf(wv.y, a1.y, fmaf(wv.z, a1.z, fmaf(wv.w, a1.w, p1))));
        p2 = fmaf(wv.x, a2.x, fmaf(wv.y, a2.y, fmaf(wv.z, a2.z, fmaf(wv.w, a2.w, p2))));
        p3 = fmaf(wv.x, a3.x, fmaf(wv.y, a3.y, fmaf(wv.z, a3.z, fmaf(wv.w, a3.w, p3))));
    }
#pragma unroll
    for (int o = 16; o; o >>= 1) {
        p0 += __shfl_xor_sync(0xffffffffu, p0, o);
        p1 += __shfl_xor_sync(0xffffffffu, p1, o);
        p2 += __shfl_xor_sync(0xffffffffu, p2, o);
        p3 += __shfl_xor_sync(0xffffffffu, p3, o);
    }
    if (lane < 4) {
        float pv = (lane == 0) ? p0 : (lane == 1) ? p1 : (lane == 2) ? p2 : p3;
        float sn, cn; sincosf(0.5f * (pv + e2rb[j]), &sn, &cn);
        g_cs[(s0 + lane) * 64 + j] = make_float2(cn, sn);
    }
    if (blockIdx.x == 0 && jg == 0 && wid == 0) {
        float re = 0.f, im = 0.f, a = 0.f;
        if (lane < 16) { re = mix[2 * lane]; im = mix[2 * lane + 1]; a = sqrtf(re * re + im * im); }
        float s = a;
#pragma unroll
        for (int o = 16; o; o >>= 1) s += __shfl_xor_sync(0xffffffffu, s, o);
        s = fmaxf(s, 1e-12f);
        if (lane < 16) g_coeffs[lane] = make_float2(re / s, im / s);
    }
    if (blockIdx.x == 0 && jg == 0 && wid == 1) {
        float sn, cn; sincosf(0.5f * qff[lane], &sn, &cn);
        g_qcs[lane] = make_float2(cn, sn);
    }
}

// =============================================================================
// k_quantum: grid 16 (batch), 512 thr (16 warps = 16 words).
// =============================================================================
__global__ void __launch_bounds__(512) k_quantum(
    const float* __restrict__ poly) {
    __shared__ float2 cs_sh[16 * 64];
    __shared__ float2 stw[16][256];
    __shared__ float2 work[256];
    __shared__ float2 accs[256];
    __shared__ float2 qcs[32];
    __shared__ float2 coef[16];
    __shared__ float  rsum[8];

    int tid = threadIdx.x, b = blockIdx.x;
    int w = tid >> 5, lane = tid & 31;

    for (int i = tid; i < 1024; i += 512) cs_sh[i] = g_cs[b * 1024 + i];
    if (tid < 32) qcs[tid] = g_qcs[tid];
    if (tid < 16) coef[tid] = g_coeffs[tid];
    __syncthreads();

    float2 st[8];
#pragma unroll 1
    for (int d = 1; d <= 3; d++) {
        if (d == 1) {
#pragma unroll
            for (int r = 0; r < 8; r++)
                st[r] = make_float2((lane == 0 && r == 0) ? 1.f : 0.f, 0.f);
        } else {
#pragma unroll
            for (int r = 0; r < 8; r++) st[r] = work[r * 32 + lane];
        }
        sim_layer(st, cs_sh + w * 64, lane);
        sim_layer(st, cs_sh + w * 64 + 32, lane);
#pragma unroll
        for (int r = 0; r < 8; r++) stw[w][r * 32 + lane] = st[r];
        __syncthreads();
        if (tid < 256) {
            float2 rd = make_float2(0.f, 0.f);
#pragma unroll
            for (int ww = 0; ww < 16; ww++) {
                float2 c = coef[ww];
                float2 s = stw[ww][tid];
                rd.x = fmaf(s.x, c.x, fmaf(-s.y, c.y, rd.x));
                rd.y = fmaf(s.x, c.y, fmaf(s.y, c.x, rd.y));
            }
            work[tid] = rd;
            float pd = poly[d];
            if (d == 1) {
                accs[tid] = make_float2(pd * rd.x + (tid == 0 ? poly[0] : 0.f), pd * rd.y);
            } else {
                float2 a = accs[tid];
                accs[tid] = make_float2(fmaf(pd, rd.x, a.x), fmaf(pd, rd.y, a.y));
            }
        }
        __syncthreads();
    }

    float invp = 1.f / (fabsf(poly[0]) + fabsf(poly[1]) + fabsf(poly[2]) + fabsf(poly[3]));
    float pn = 0.f;
    float2 v = make_float2(0.f, 0.f);
    if (tid < 256) {
        float2 a = accs[tid];
        v = make_float2(a.x * invp, a.y * invp);
        pn = v.x * v.x + v.y * v.y;
    }
#pragma unroll
    for (int o = 16; o; o >>= 1) pn += __shfl_xor_sync(0xffffffffu, pn, o);
    if (tid < 256 && lane == 0) rsum[w] = pn;
    __syncthreads();
    float tot = rsum[0] + rsum[1] + rsum[2] + rsum[3] +
                rsum[4] + rsum[5] + rsum[6] + rsum[7];
    float fp = sqrtf(tot);
    if (tid == 0) g_fp[b] = fp;
    float inv = 1.f / fmaxf(fp, 1e-12f);
    if (tid < 256) work[tid] = make_float2(v.x * inv, v.y * inv);
    __syncthreads();

    if (w == 0) {
#pragma unroll
        for (int r = 0; r < 8; r++) st[r] = work[r * 32 + lane];
        sim_layer(st, qcs, lane);

#define MEAS_REG(W_) { constexpr int m = 1 << (7 - (W_)); \
        float cr = 0.f, ci = 0.f, zz = 0.f; \
        _Pragma("unroll") \
        for (int r = 0; r < 8; r++) if (!(r & m)) { \
            float2 a0 = st[r], a1 = st[r | m]; \
            cr += a0.x * a1.x + a0.y * a1.y; \
            ci += a0.x * a1.y - a0.y * a1.x; \
            zz += a0.x * a0.x + a0.y * a0.y - a1.x * a1.x - a1.y * a1.y; } \
        _Pragma("unroll") \
        for (int o = 16; o; o >>= 1) { \
            cr += __shfl_xor_sync(0xffffffffu, cr, o); \
            ci += __shfl_xor_sync(0xffffffffu, ci, o); \
            zz += __shfl_xor_sync(0xffffffffu, zz, o); } \
        if (lane == 0) { g_ex[b * 24 + (W_)] = 2.f * cr; \
                         g_ex[b * 24 + 8 + (W_)] = 2.f * ci; \
                         g_ex[b * 24 + 16 + (W_)] = zz; } }

#define MEAS_LANE(W_) { constexpr int lm = 1 << (4 - (W_)); \
        bool hi = (lane & lm) != 0; \
        float cr = 0.f, ci = 0.f, zz = 0.f; \
        _Pragma("unroll") \
        for (int r = 0; r < 8; r++) { \
            float px = __shfl_xor_sync(0xffffffffu, st[r].x, lm); \
            float py = __shfl_xor_sync(0xffffffffu, st[r].y, lm); \
            float n2 = st[r].x * st[r].x + st[r].y * st[r].y; \
            if (!hi) { cr += st[r].x * px + st[r].y * py; \
                       ci += st[r].x * py - st[r].y * px; zz += n2; } \
            else zz -= n2; } \
        _Pragma("unroll") \
        for (int o = 16; o; o >>= 1) { \
            cr += __shfl_xor_sync(0xffffffffu, cr, o); \
            ci += __shfl_xor_sync(0xffffffffu, ci, o); \
            zz += __shfl_xor_sync(0xffffffffu, zz, o); } \
        if (lane == 0) { g_ex[b * 24 + (W_)] = 2.f * cr; \
                         g_ex[b * 24 + 8 + (W_)] = 2.f * ci; \
                         g_ex[b * 24 + 16 + (W_)] = zz; } }

        MEAS_LANE(0); MEAS_LANE(1); MEAS_LANE(2); MEAS_LANE(3); MEAS_LANE(4);
        MEAS_REG(5);  MEAS_REG(6);  MEAS_REG(7);
    }
}

// =============================================================================
// k_ff1: grid 16 (batch), 512 thr: h = relu(ex @ ff1W^T + b) -> packed g_hp
// =============================================================================
__global__ void __launch_bounds__(512) k_ff1(const float* __restrict__ ff1W,
                                             const float* __restrict__ ff1b) {
    __shared__ float ex[24];
    int tid = threadIdx.x, b = blockIdx.x;
    if (tid < 24) ex[tid] = g_ex[b * 24 + tid];
    __syncthreads();
    float h = ff1b[tid];
    const float* wr = ff1W + tid * 24;
#pragma unroll
    for (int m = 0; m < 24; m++) h = fmaf(ex[m], wr[m], h);
    h = fmaxf(h, 0.f);
    ((float*)&g_hp[tid * 8 + (b >> 1)])[b & 1] = h;
}

// =============================================================================
// k_ff2: 131 blocks x 256 thr. Warp = (bp-group of 2 slots) x (row-half of 192).
// Lane owns 6 rows (i*32+lane). h-LDS cut 4x vs uniform scheme; each h load
// feeds 12 FFMA2. cp.async double-buffered W2 staging.
// =============================================================================
#define FF2_RPB    384                       // rows per block (192 per half)
#define FF2_NB     131                       // ceil(50257/384)
#define FF2_ST4    9                         // float4 per row per chunk (8 + pad)
#define FF2_BUF4   (FF2_RPB * FF2_ST4)       // float4 per buffer = 3456
#define FF2_SMEM   (32768 + 2 * FF2_BUF4 * 16)

__device__ __forceinline__ void ff2_stage(float4* buf, const float* __restrict__ W2,
                                          int base, int k0, int tid) {
    uint32_t sb = (uint32_t)__cvta_generic_to_shared(buf);
#pragma unroll
    for (int it = 0; it < 12; it++) {        // 3072 cp16 / 256 threads
        int u = tid + it * 256;
        int rr = u >> 3, q = u & 7;
        int v = base + rr; if (v >= VQ) v = VQ - 1;
        cp16(sb + (uint32_t)(rr * FF2_ST4 + q) * 16,
             W2 + (size_t)v * EMBQ + k0 + q * 4);
    }
}

__global__ void __launch_bounds__(256, 1) k_ff2(const float* __restrict__ W2,
                                                const float* __restrict__ b2,
                                                float* __restrict__ out, int out_size) {
    extern __shared__ char dsm[];
    ull*    hsh  = (ull*)dsm;                            // 32 KB
    float4* sW0  = (float4*)(dsm + 32768);
    float4* sW1  = sW0 + FF2_BUF4;
    const ulonglong2* hsh2 = (const ulonglong2*)hsh;

    int t = threadIdx.x;
    int wid = t >> 5, lane = t & 31;
    int g  = wid & 3;                // bp-group: slots 2g, 2g+1 (batches 4g..4g+3)
    int rh = wid >> 2;               // row-half
    int base = blockIdx.x * FF2_RPB;
    int rbase = rh * 192 + lane;     // local row of i=0

    // load h (32 KB) as ull2
    {
        const ulonglong2* gp = (const ulonglong2*)g_hp;
        ulonglong2* sp = (ulonglong2*)hsh;
#pragma unroll
        for (int it = 0; it < 8; it++) sp[t + it * 256] = gp[t + it * 256];
    }

    ff2_stage(sW0, W2, base, 0, t);
    asm volatile("cp.async.commit_group;");

    ull acc[6][2];
#pragma unroll
    for (int i = 0; i < 6; i++) { acc[i][0] = 0ull; acc[i][1] = 0ull; }

#pragma unroll 1
    for (int c = 0; c < 16; c++) {
        if (c < 15) {
            ff2_stage((c & 1) ? sW0 : sW1, W2, base, (c + 1) * 32, t);
            asm volatile("cp.async.commit_group;");
            asm volatile("cp.async.wait_group 1;");
        } else {
            asm volatile("cp.async.wait_group 0;");
        }
        __syncthreads();
        const float4* b4 = (c & 1) ? sW1 : sW0;
        int k0 = c * 32;
#pragma unroll 4
        for (int k4 = 0; k4 < 8; k4++) {
            ulonglong2 h[4];
#pragma unroll
            for (int j = 0; j < 4; j++) h[j] = hsh2[(size_t)(k0 + k4 * 4 + j) * 4 + g];
#pragma unroll
            for (int i = 0; i < 6; i++) {
                float4 wv = b4[(rbase + i * 32) * FF2_ST4 + k4];
                ull w0 = dup2(wv.x), w1 = dup2(wv.y), w2 = dup2(wv.z), w3 = dup2(wv.w);
                ffma2(acc[i][0], h[0].x, w0); ffma2(acc[i][1], h[0].y, w0);
                ffma2(acc[i][0], h[1].x, w1); ffma2(acc[i][1], h[1].y, w1);
                ffma2(acc[i][0], h[2].x, w2); ffma2(acc[i][1], h[2].y, w2);
                ffma2(acc[i][0], h[3].x, w3); ffma2(acc[i][1], h[3].y, w3);
            }
        }
        __syncthreads();
    }

    int b00 = 4 * g, b01 = 4 * g + 1, b10 = 4 * g + 2, b11 = 4 * g + 3;
#pragma unroll
    for (int i = 0; i < 6; i++) {
        int v = base + rbase + i * 32;
        if (v < VQ) {
            float bias = b2[v];
            float lo, hi;
            unpack2(acc[i][0], lo, hi);
            out[(size_t)b00 * VQ + v] = lo + bias;
            out[(size_t)b01 * VQ + v] = hi + bias;
            unpack2(acc[i][1], lo, hi);
            out[(size_t)b10 * VQ + v] = lo + bias;
            out[(size_t)b11 * VQ + v] = hi + bias;
        }
    }

    if (blockIdx.x == 0 && t == 0 && out_size > 16 * VQ) {
        float s = 0.f;
        for (int b = 0; b < 16; b++) s += g_fp[b];
        out[16 * VQ] = s * (1.f / 16.f);
    }
}

// ------------------------------ launch ---------------------------------------
extern "C" void kernel_launch(void* const* d_in, const int* in_sizes, int n_in,
                              void* d_out, int out_size) {
    const int*   x    = (const int*)  d_in[0];
    const float* embW = (const float*)d_in[1];
    const float* e2rW = (const float*)d_in[2];
    const float* e2rb = (const float*)d_in[3];
    const float* poly = (const float*)d_in[4];
    const float* mix  = (const float*)d_in[5];
    const float* qff  = (const float*)d_in[6];
    const float* ff1W = (const float*)d_in[7];
    const float* ff1b = (const float*)d_in[8];
    const float* W2   = (const float*)d_in[9];
    const float* b2   = (const float*)d_in[10];
    float* out = (float*)d_out;

    cudaFuncSetAttribute(k_ff2, cudaFuncAttributeMaxDynamicSharedMemorySize, FF2_SMEM);

    dim3 eg(64, 8);
    k_emb<<<eg, 256>>>(x, embW, e2rW, e2rb, mix, qff);
    k_quantum<<<16, 512>>>(poly);
    k_ff1<<<16, 512>>>(ff1W, ff1b);
    k_ff2<<<FF2_NB, 256, FF2_SMEM>>>(W2, b2, out, out_size);
}